// round 2
// baseline (speedup 1.0000x reference)
#include <cuda_runtime.h>

// AdaptiveFilter: per-pixel learned bilateral filter, register-blocked PX=4.
// out_c(p) = sum_k x_c(p+dk) * e_k / sum_k e_k,
//   e_k = 2^( w_k*log2e - 50*log2e * d_k^2 ),  d_k = sum_c |g_c(p+dk)-g_c(p)|
// (softmax normalizer cancels in the ratio.)

namespace {
constexpr int B = 2, C = 3, H = 512, W = 512;
constexpr int BX = 16, BY = 16;     // thread block
constexpr int PX = 4;               // pixels per thread (x)
constexpr int TW = BX * PX;         // 64-pixel tile width
constexpr int TH = BY;              // 16-pixel tile height
constexpr int HALO = 3;
constexpr int SW = TW + 2 * HALO;   // 70
constexpr int SH = TH + 2 * HALO;   // 22
constexpr float LOG2E = 1.4426950408889634f;
constexpr float NC = -50.0f * LOG2E;  // -72.134752...
}

__device__ __forceinline__ float ex2f(float v) {
    float r;
    asm("ex2.approx.f32 %0, %1;" : "=f"(r) : "f"(v));
    return r;
}

__global__ __launch_bounds__(BX * BY)
void adaptive_filter_kernel(const float* __restrict__ x,
                            const float* __restrict__ g,
                            const float* __restrict__ w0,
                            float* __restrict__ out) {
    // Packed shared tiles: sgx = (g0,g1,g2,x0), sx2 = (x1,x2). +1 pad col.
    __shared__ float4 sgx[SH][SW + 1];
    __shared__ float2 sx2[SH][SW + 1];

    const int b   = blockIdx.z;
    const int h0  = blockIdx.y * TH;
    const int w0c = blockIdx.x * TW;
    const int tid = threadIdx.y * BX + threadIdx.x;

    const float* __restrict__ gb = g + (size_t)b * C * H * W;
    const float* __restrict__ xb = x + (size_t)b * C * H * W;

    // Cooperative halo load with reflect padding (pad=3 << 512, one reflection).
    for (int idx = tid; idx < SH * SW; idx += BX * BY) {
        const int ty = idx / SW;
        const int tx = idx - ty * SW;
        int gy = h0 + ty - HALO;
        gy = gy < 0 ? -gy : (gy >= H ? 2 * H - 2 - gy : gy);
        int gx = w0c + tx - HALO;
        gx = gx < 0 ? -gx : (gx >= W ? 2 * W - 2 - gx : gx);
        const int p = gy * W + gx;
        sgx[ty][tx] = make_float4(gb[p], gb[H * W + p], gb[2 * H * W + p], xb[p]);
        sx2[ty][tx] = make_float2(xb[H * W + p], xb[2 * H * W + p]);
    }
    __syncthreads();

    const int h   = h0 + threadIdx.y;
    const int wpx = w0c + threadIdx.x * PX;   // first of this thread's 4 pixels

    // w0 logits: 16 floats per pixel = 4 float4 rows; reloaded per kernel-row
    // (rows repeat 0,1,2,3,2,1,0 -> L1 hits) to keep register pressure down.
    const float4* __restrict__ wbase =
        reinterpret_cast<const float4*>(w0) +
        ((size_t)b * H * W + (size_t)h * W + wpx) * 4;

    // Center guidance per pixel.
    float gcx[PX], gcy[PX], gcz[PX];
#pragma unroll
    for (int p = 0; p < PX; ++p) {
        const float4 c0 = sgx[threadIdx.y + HALO][threadIdx.x * PX + HALO + p];
        gcx[p] = c0.x; gcy[p] = c0.y; gcz[p] = c0.z;
    }

    float n0[PX], n1[PX], n2[PX], den[PX];
#pragma unroll
    for (int p = 0; p < PX; ++p) { n0[p] = n1[p] = n2[p] = den[p] = 0.f; }

#pragma unroll
    for (int i = 0; i < 7; ++i) {
        const int hi = i < 4 ? i : 6 - i;  // reflect of half-kernel rows

        // Per-pixel logits for this row, pre-scaled by log2(e).
        float wl[PX][4];
#pragma unroll
        for (int p = 0; p < PX; ++p) {
            const float4 wv = __ldg(&wbase[p * 4 + hi]);
            wl[p][0] = wv.x * LOG2E;
            wl[p][1] = wv.y * LOG2E;
            wl[p][2] = wv.z * LOG2E;
            wl[p][3] = wv.w * LOG2E;
        }

        // Load the 10 shared columns this thread's 4 pixels need for row i.
        float4 a[PX + 6];
        float2 u[PX + 6];
#pragma unroll
        for (int j = 0; j < PX + 6; ++j) {
            a[j] = sgx[threadIdx.y + i][threadIdx.x * PX + j];
            u[j] = sx2[threadIdx.y + i][threadIdx.x * PX + j];
        }

#pragma unroll
        for (int p = 0; p < PX; ++p) {
#pragma unroll
            for (int j = 0; j < 7; ++j) {
                const int hj = j < 4 ? j : 6 - j;  // reflect of half-kernel cols
                const float4 v = a[p + j];
                const float2 t = u[p + j];
                const float d = fabsf(v.x - gcx[p]) + fabsf(v.y - gcy[p]) +
                                fabsf(v.z - gcz[p]);
                const float e = ex2f(fmaf(d * d, NC, wl[p][hj]));
                n0[p] = fmaf(v.w, e, n0[p]);
                n1[p] = fmaf(t.x, e, n1[p]);
                n2[p] = fmaf(t.y, e, n2[p]);
                den[p] += e;
            }
        }
    }

    float inv[PX];
#pragma unroll
    for (int p = 0; p < PX; ++p) inv[p] = __fdividef(1.0f, den[p]);

    const size_t o = ((size_t)b * C * H + (size_t)h) * W + wpx;
    *reinterpret_cast<float4*>(out + o) =
        make_float4(n0[0] * inv[0], n0[1] * inv[1], n0[2] * inv[2], n0[3] * inv[3]);
    *reinterpret_cast<float4*>(out + o + (size_t)H * W) =
        make_float4(n1[0] * inv[0], n1[1] * inv[1], n1[2] * inv[2], n1[3] * inv[3]);
    *reinterpret_cast<float4*>(out + o + (size_t)2 * H * W) =
        make_float4(n2[0] * inv[0], n2[1] * inv[1], n2[2] * inv[2], n2[3] * inv[3]);
}

extern "C" void kernel_launch(void* const* d_in, const int* in_sizes, int n_in,
                              void* d_out, int out_size) {
    const float* x  = (const float*)d_in[0];
    const float* g  = (const float*)d_in[1];
    const float* w0 = (const float*)d_in[2];
    float* out = (float*)d_out;

    dim3 block(BX, BY);
    dim3 grid(W / TW, H / TH, B);
    adaptive_filter_kernel<<<grid, block>>>(x, g, w0, out);
}

// round 3
// speedup vs baseline: 1.9478x; 1.9478x over previous
#include <cuda_runtime.h>

// AdaptiveFilter: per-pixel learned bilateral filter, vertical register blocking PY=2.
// out_c(p) = sum_k x_c(p+dk) * e_k / sum_k e_k,
//   e_k = 2^( w_k*log2e - 50*log2e * d_k^2 ),  d_k = sum_c |g_c(p+dk)-g_c(p)|
// (softmax normalizer cancels in the ratio.)
// Two vertically adjacent pixels per thread share the same shared-memory row
// reads (8 rows x 7 cols serve both pixels' 98 taps).

namespace {
constexpr int B = 2, C = 3, H = 512, W = 512;
constexpr int BX = 16, BY = 8;       // 128 threads
constexpr int PY = 2;                // pixels per thread (vertical)
constexpr int TW = BX;               // 16
constexpr int TH = BY * PY;          // 16
constexpr int HALO = 3;
constexpr int SW = TW + 2 * HALO;    // 22
constexpr int SH = TH + 2 * HALO;    // 22
constexpr float LOG2E = 1.4426950408889634f;
constexpr float NC = -50.0f * LOG2E; // -72.134752...
}

__device__ __forceinline__ float ex2f(float v) {
    float r;
    asm("ex2.approx.f32 %0, %1;" : "=f"(r) : "f"(v));
    return r;
}

__global__ __launch_bounds__(BX * BY, 6)
void adaptive_filter_kernel(const float* __restrict__ x,
                            const float* __restrict__ g,
                            const float* __restrict__ w0,
                            float* __restrict__ out) {
    // Packed shared tiles: sgx = (g0,g1,g2,x0), sx2 = (x1,x2). +1 pad col.
    __shared__ float4 sgx[SH][SW + 1];
    __shared__ float2 sx2[SH][SW + 1];

    const int b   = blockIdx.z;
    const int h0  = blockIdx.y * TH;
    const int w0c = blockIdx.x * TW;
    const int tid = threadIdx.y * BX + threadIdx.x;

    const float* __restrict__ gb = g + (size_t)b * C * H * W;
    const float* __restrict__ xb = x + (size_t)b * C * H * W;

    // Cooperative halo load with reflect padding (pad=3 << 512, one reflection).
    for (int idx = tid; idx < SH * SW; idx += BX * BY) {
        const int ty = idx / SW;
        const int tx = idx - ty * SW;
        int gy = h0 + ty - HALO;
        gy = gy < 0 ? -gy : (gy >= H ? 2 * H - 2 - gy : gy);
        int gx = w0c + tx - HALO;
        gx = gx < 0 ? -gx : (gx >= W ? 2 * W - 2 - gx : gx);
        const int p = gy * W + gx;
        sgx[ty][tx] = make_float4(gb[p], gb[H * W + p], gb[2 * H * W + p], xb[p]);
        sx2[ty][tx] = make_float2(xb[H * W + p], xb[2 * H * W + p]);
    }
    __syncthreads();

    const int tx  = threadIdx.x;
    const int py0 = threadIdx.y * PY;       // tile-local row of pixel 0
    const int h   = h0 + py0;
    const int w   = w0c + tx;

    // Per-pixel half-kernel logits: 16 contiguous floats = 4 float4 rows.
    // Reloaded per window-row (rows repeat 0,1,2,3,2,1,0 -> L1 hits).
    const float4* __restrict__ wb0 =
        reinterpret_cast<const float4*>(w0) + ((size_t)b * H * W + (size_t)h * W + w) * 4;
    const float4* __restrict__ wb1 = wb0 + (size_t)W * 4;

    // Center guidance per pixel.
    const float4 c0 = sgx[py0 + HALO][tx + HALO];
    const float4 c1 = sgx[py0 + 1 + HALO][tx + HALO];

    float n0[PY] = {0.f, 0.f}, n1[PY] = {0.f, 0.f},
          n2[PY] = {0.f, 0.f}, den[PY] = {0.f, 0.f};

#pragma unroll
    for (int i = 0; i < 8; ++i) {            // absolute window rows py0+i
        const int row = py0 + i;

        // One shared-row read serves both pixels.
        float4 a[7];
        float2 u[7];
#pragma unroll
        for (int j = 0; j < 7; ++j) {
            a[j] = sgx[row][tx + j];
            u[j] = sx2[row][tx + j];
        }

        // Kernel-row logits for each valid pixel (pre-scaled by log2 e).
        float wl0[4], wl1[4];
        if (i <= 6) {                        // pixel 0: kernel row i
            const int hi = i < 4 ? i : 6 - i;
            const float4 t = __ldg(&wb0[hi]);
            wl0[0] = t.x * LOG2E; wl0[1] = t.y * LOG2E;
            wl0[2] = t.z * LOG2E; wl0[3] = t.w * LOG2E;
        }
        if (i >= 1) {                        // pixel 1: kernel row i-1
            const int kr = i - 1;
            const int hi = kr < 4 ? kr : 6 - kr;
            const float4 t = __ldg(&wb1[hi]);
            wl1[0] = t.x * LOG2E; wl1[1] = t.y * LOG2E;
            wl1[2] = t.z * LOG2E; wl1[3] = t.w * LOG2E;
        }

#pragma unroll
        for (int j = 0; j < 7; ++j) {
            const int hj = j < 4 ? j : 6 - j;
            const float4 v = a[j];
            const float2 t = u[j];
            if (i <= 6) {
                const float d = fabsf(v.x - c0.x) + fabsf(v.y - c0.y) + fabsf(v.z - c0.z);
                const float e = ex2f(fmaf(d * d, NC, wl0[hj]));
                n0[0] = fmaf(v.w, e, n0[0]);
                n1[0] = fmaf(t.x, e, n1[0]);
                n2[0] = fmaf(t.y, e, n2[0]);
                den[0] += e;
            }
            if (i >= 1) {
                const float d = fabsf(v.x - c1.x) + fabsf(v.y - c1.y) + fabsf(v.z - c1.z);
                const float e = ex2f(fmaf(d * d, NC, wl1[hj]));
                n0[1] = fmaf(v.w, e, n0[1]);
                n1[1] = fmaf(t.x, e, n1[1]);
                n2[1] = fmaf(t.y, e, n2[1]);
                den[1] += e;
            }
        }
    }

    const float i0 = __fdividef(1.0f, den[0]);
    const float i1 = __fdividef(1.0f, den[1]);

    const size_t o = ((size_t)b * C * H + (size_t)h) * W + w;
    out[o]                       = n0[0] * i0;
    out[o + (size_t)H * W]       = n1[0] * i0;
    out[o + (size_t)2 * H * W]   = n2[0] * i0;
    out[o + W]                   = n0[1] * i1;
    out[o + W + (size_t)H * W]   = n1[1] * i1;
    out[o + W + (size_t)2 * H * W] = n2[1] * i1;
}

extern "C" void kernel_launch(void* const* d_in, const int* in_sizes, int n_in,
                              void* d_out, int out_size) {
    const float* x  = (const float*)d_in[0];
    const float* g  = (const float*)d_in[1];
    const float* w0 = (const float*)d_in[2];
    float* out = (float*)d_out;

    dim3 block(BX, BY);
    dim3 grid(W / TW, H / TH, B);
    adaptive_filter_kernel<<<grid, block>>>(x, g, w0, out);
}